// round 2
// baseline (speedup 1.0000x reference)
#include <cuda_runtime.h>
#include <cstdint>

#define BB 16384
#define TT 2048
#define HH 16

// Scratch: x transposed to [T, B] so the GRU kernel's per-step load is coalesced.
__device__ float g_xT[(size_t)BB * (size_t)TT];

typedef unsigned long long ull;

__device__ __forceinline__ ull pk2(float a, float b) {
    ull r; asm("mov.b64 %0, {%1, %2};" : "=l"(r) : "f"(a), "f"(b)); return r;
}
__device__ __forceinline__ void upk2(ull v, float& a, float& b) {
    asm("mov.b64 {%0, %1}, %2;" : "=f"(a), "=f"(b) : "l"(v));
}
__device__ __forceinline__ ull ffma2(ull a, ull b, ull c) {
    ull d; asm("fma.rn.f32x2 %0, %1, %2, %3;" : "=l"(d) : "l"(a), "l"(b), "l"(c)); return d;
}
__device__ __forceinline__ float ex2f(float x) {
    float y; asm("ex2.approx.f32 %0, %1;" : "=f"(y) : "f"(x)); return y;
}
__device__ __forceinline__ float rcpf(float x) {
    float y; asm("rcp.approx.f32 %0, %1;" : "=f"(y) : "f"(x)); return y;
}
// sigmoid(x) = 1 / (1 + 2^(-x*log2e))
__device__ __forceinline__ float sigmf(float x) {
    return rcpf(1.0f + ex2f(-1.4426950408889634f * x));
}
// tanh(x) = 1 - 2/(e^{2x}+1), e^{2x} = 2^(2x*log2e)
__device__ __forceinline__ float tanhf_fast(float x) {
    float e = ex2f(2.8853900817779268f * x);
    return fmaf(-2.0f, rcpf(e + 1.0f), 1.0f);
}

// ---------------------------------------------------------------------------
// Kernel 1: transpose x [B, T] -> g_xT [T, B]
// ---------------------------------------------------------------------------
__global__ void transpose_kernel(const float* __restrict__ x) {
    __shared__ float tile[32][33];
    int t0 = blockIdx.x * 32;
    int b0 = blockIdx.y * 32;
    int tx = threadIdx.x, ty = threadIdx.y;
#pragma unroll
    for (int i = 0; i < 4; i++) {
        tile[ty + i * 8][tx] = x[(size_t)(b0 + ty + i * 8) * TT + (t0 + tx)];
    }
    __syncthreads();
#pragma unroll
    for (int i = 0; i < 4; i++) {
        g_xT[(size_t)(t0 + ty + i * 8) * BB + (b0 + tx)] = tile[tx][ty + i * 8];
    }
}

// ---------------------------------------------------------------------------
// Kernel 2: GRU scan, 4-way hidden split.
//   - A 4-lane GROUP handles 2 batch elements packed as f32x2.
//   - Lane quarter q = lane&3 owns hidden indices j = 4q..4q+3 and computes
//     gate rows {j, 16+j, 32+j} for both packed elements.
//   - hx[16] holds all 16 hidden f32x2 values arranged in blocks of 4 with
//     block order [q, q^1, q^2, q^3]; weights in SMEM are k-permuted per q
//     so all lanes run identical code.
//   - h all-gathered in the group via 2-stage butterfly shuffle each step.
// ---------------------------------------------------------------------------

__device__ __forceinline__ ull dot16(const ull* __restrict__ wr, const ull hx[16], ull acc) {
#pragma unroll
    for (int k2 = 0; k2 < 8; k2++) {
        ulonglong2 w = ((const ulonglong2*)wr)[k2];
        acc = ffma2(w.x, hx[2 * k2], acc);
        acc = ffma2(w.y, hx[2 * k2 + 1], acc);
    }
    return acc;
}

__global__ __launch_bounds__(128)
void gru_kernel(const float* __restrict__ w_ih, const float* __restrict__ w_hh,
                const float* __restrict__ b_ih, const float* __restrict__ b_hh,
                const float* __restrict__ w_fc, const float* __restrict__ b_fc,
                float* __restrict__ out)
{
    // w4p[q][r][kk]: r in [0,12): gate = r/4 (0=r,1=z,2=n), jj = r%4.
    // Row = gate*16 + q*4 + jj. k-order: kk -> j_src = ((q ^ (kk>>2))<<2) | (kk&3).
    __shared__ ull w4p[4][12][16];

    int tid = threadIdx.x;
    for (int idx = tid; idx < 4 * 12 * 16; idx += 128) {
        int q    = idx / 192;
        int rem  = idx % 192;
        int r    = rem / 16;
        int kk   = rem % 16;
        int gate = r >> 2;
        int jj   = r & 3;
        int row  = gate * 16 + q * 4 + jj;
        int srck = ((q ^ (kk >> 2)) << 2) | (kk & 3);
        float v  = w_hh[row * 16 + srck];
        w4p[q][r][kk] = pk2(v, v);
    }
    __syncthreads();

    int g    = blockIdx.x * 128 + tid;
    int q    = g & 3;
    int p    = g >> 2;        // batch-pair index; elements 2p, 2p+1
    int base = 2 * p;

    // Per-thread constants for its 4 absolute hidden indices j = q*4 + jj
    float wir[4], wiz[4], win[4], bsr[4], bsz[4], bin[4], bhn[4];
#pragma unroll
    for (int jj = 0; jj < 4; jj++) {
        int j   = q * 4 + jj;
        wir[jj] = __ldg(&w_ih[j]);
        wiz[jj] = __ldg(&w_ih[16 + j]);
        win[jj] = __ldg(&w_ih[32 + j]);
        bsr[jj] = __ldg(&b_ih[j])      + __ldg(&b_hh[j]);
        bsz[jj] = __ldg(&b_ih[16 + j]) + __ldg(&b_hh[16 + j]);
        bin[jj] = __ldg(&b_ih[32 + j]);
        bhn[jj] = __ldg(&b_hh[32 + j]);
    }
    const ull* wb = &w4p[q][0][0];

    // hx blocks of 4: [own(q), q^1, q^2, q^3]
    ull hx[16];
#pragma unroll
    for (int k = 0; k < 16; k++) hx[k] = 0ull;

    const float2* xp = ((const float2*)g_xT) + p;
    float2 xv = __ldg(&xp[0]);

    for (int t = 0; t < TT; t++) {
        float x0 = xv.x, x1 = xv.y;
        int tn = (t < TT - 1) ? (t + 1) : t;
        float2 xnext = __ldg(&xp[(size_t)tn * (BB / 2)]);

        float r0a[4], r1a[4], z0a[4], z1a[4];

        // r gate (rows 0..3 of this quarter's table)
#pragma unroll
        for (int jj = 0; jj < 4; jj++) {
            ull acc = pk2(fmaf(x0, wir[jj], bsr[jj]), fmaf(x1, wir[jj], bsr[jj]));
            acc = dot16(wb + jj * 16, hx, acc);
            float a0, a1; upk2(acc, a0, a1);
            r0a[jj] = sigmf(a0);
            r1a[jj] = sigmf(a1);
        }
        // z gate (rows 4..7)
#pragma unroll
        for (int jj = 0; jj < 4; jj++) {
            ull acc = pk2(fmaf(x0, wiz[jj], bsz[jj]), fmaf(x1, wiz[jj], bsz[jj]));
            acc = dot16(wb + (4 + jj) * 16, hx, acc);
            float a0, a1; upk2(acc, a0, a1);
            z0a[jj] = sigmf(a0);
            z1a[jj] = sigmf(a1);
        }
        // n gate (rows 8..11) + h update (old h used by all dots -> safe: each
        // jj's dot uses hx which is only overwritten after all reads of block 0)
        ull hnew[4];
#pragma unroll
        for (int jj = 0; jj < 4; jj++) {
            ull acc = pk2(bhn[jj], bhn[jj]);          // gh_n accumulates b_hh_n
            acc = dot16(wb + (8 + jj) * 16, hx, acc);
            float gh0, gh1; upk2(acc, gh0, gh1);
            float pre0 = fmaf(r0a[jj], gh0, fmaf(x0, win[jj], bin[jj]));
            float pre1 = fmaf(r1a[jj], gh1, fmaf(x1, win[jj], bin[jj]));
            float n0 = tanhf_fast(pre0);
            float n1 = tanhf_fast(pre1);
            float h0, h1; upk2(hx[jj], h0, h1);
            h0 = fmaf(z0a[jj], h0 - n0, n0);          // (1-z)n + z h
            h1 = fmaf(z1a[jj], h1 - n1, n1);
            hnew[jj] = pk2(h0, h1);
        }
#pragma unroll
        for (int jj = 0; jj < 4; jj++) hx[jj] = hnew[jj];

        // butterfly all-gather within the 4-lane group:
        // stage 1 (xor 1): own block -> block 1
#pragma unroll
        for (int jj = 0; jj < 4; jj++) {
            hx[4 + jj] = __shfl_xor_sync(0xffffffffu, hx[jj], 1);
        }
        // stage 2 (xor 2): blocks 0..1 -> blocks 2..3
#pragma unroll
        for (int jj = 0; jj < 8; jj++) {
            hx[8 + jj] = __shfl_xor_sync(0xffffffffu, hx[jj], 2);
        }

        xv = xnext;
    }

    // FC epilogue: out[b] = sum_j h[b][j] * w_fc[j] + b_fc
    float p0 = 0.0f, p1 = 0.0f;
#pragma unroll
    for (int jj = 0; jj < 4; jj++) {
        float wf = __ldg(&w_fc[q * 4 + jj]);
        float h0, h1; upk2(hx[jj], h0, h1);
        p0 = fmaf(h0, wf, p0);
        p1 = fmaf(h1, wf, p1);
    }
    p0 += __shfl_xor_sync(0xffffffffu, p0, 1);
    p1 += __shfl_xor_sync(0xffffffffu, p1, 1);
    p0 += __shfl_xor_sync(0xffffffffu, p0, 2);
    p1 += __shfl_xor_sync(0xffffffffu, p1, 2);
    if (q == 0) {
        float bf = __ldg(b_fc);
        float2 o;
        o.x = p0 + bf;
        o.y = p1 + bf;
        *(float2*)(out + base) = o;
    }
}

// ---------------------------------------------------------------------------
extern "C" void kernel_launch(void* const* d_in, const int* in_sizes, int n_in,
                              void* d_out, int out_size)
{
    const float* x    = (const float*)d_in[0];
    const float* w_ih = (const float*)d_in[1];
    const float* w_hh = (const float*)d_in[2];
    const float* b_ih = (const float*)d_in[3];
    const float* b_hh = (const float*)d_in[4];
    const float* w_fc = (const float*)d_in[5];
    const float* b_fc = (const float*)d_in[6];
    float* out = (float*)d_out;

    dim3 tb(32, 8);
    dim3 tg(TT / 32, BB / 32);
    transpose_kernel<<<tg, tb>>>(x);

    // 16384 batch / 2 per group * 4 lanes per group = 32768 threads
    gru_kernel<<<256, 128>>>(w_ih, w_hh, b_ih, b_hh, w_fc, b_fc, out);
}

// round 3
// speedup vs baseline: 3.0685x; 3.0685x over previous
#include <cuda_runtime.h>
#include <cstdint>

#define BB 16384
#define TT 2048

// Scratch: x transposed to [T, B] so the GRU kernel's per-step load is coalesced.
__device__ float g_xT[(size_t)BB * (size_t)TT];

typedef unsigned long long ull;

__device__ __forceinline__ ull pk2(float a, float b) {
    ull r; asm("mov.b64 %0, {%1, %2};" : "=l"(r) : "f"(a), "f"(b)); return r;
}
__device__ __forceinline__ void upk2(ull v, float& a, float& b) {
    asm("mov.b64 {%0, %1}, %2;" : "=f"(a), "=f"(b) : "l"(v));
}
__device__ __forceinline__ ull ffma2(ull a, ull b, ull c) {
    ull d; asm("fma.rn.f32x2 %0, %1, %2, %3;" : "=l"(d) : "l"(a), "l"(b), "l"(c)); return d;
}
// MUFU.TANH — single-instruction tanh (sm_75+)
__device__ __forceinline__ float tanh_mufu(float x) {
    float y; asm("tanh.approx.f32 %0, %1;" : "=f"(y) : "f"(x)); return y;
}
// sigmoid with the 0.5 input scale PRE-FOLDED into weights/biases:
// caller passes a = 0.5*(gi+gh); sigmoid = 0.5*tanh(a) + 0.5
__device__ __forceinline__ float sig_from_half(float a) {
    return fmaf(0.5f, tanh_mufu(a), 0.5f);
}

// ---------------------------------------------------------------------------
// Kernel 1: transpose x [B, T] -> g_xT [T, B]
// ---------------------------------------------------------------------------
__global__ void transpose_kernel(const float* __restrict__ x) {
    __shared__ float tile[32][33];
    int t0 = blockIdx.x * 32;
    int b0 = blockIdx.y * 32;
    int tx = threadIdx.x, ty = threadIdx.y;
#pragma unroll
    for (int i = 0; i < 4; i++) {
        tile[ty + i * 8][tx] = x[(size_t)(b0 + ty + i * 8) * TT + (t0 + tx)];
    }
    __syncthreads();
#pragma unroll
    for (int i = 0; i < 4; i++) {
        g_xT[(size_t)(t0 + ty + i * 8) * BB + (b0 + tx)] = tile[tx][ty + i * 8];
    }
}

// ---------------------------------------------------------------------------
// Kernel 2: GRU scan, 4-way hidden split, bank-conflict-free weight tables.
//   - 4-lane group handles a packed batch pair (f32x2). Lane q = lane&3 owns
//     hidden indices 4q..4q+3 and gate rows {j, 16+j, 32+j}.
//   - Per-q weight tables padded to 196 ull (1568 B): q-stride ≡ 8 banks mod 32
//     so the 4 concurrent 16B LDS requests hit disjoint bank quads.
//   - r/z gate weights+biases pre-scaled by 0.5 (sigmoid via tanh identity).
//   - h all-gathered in the group via 2-stage butterfly shuffle each step.
// ---------------------------------------------------------------------------

#define QSTRIDE 196   // 12*16 + 4 pad (ull units)

__device__ __forceinline__ ull dot16(const ull* __restrict__ wr, const ull hx[16], ull acc) {
#pragma unroll
    for (int k2 = 0; k2 < 8; k2++) {
        ulonglong2 w = ((const ulonglong2*)wr)[k2];
        acc = ffma2(w.x, hx[2 * k2], acc);
        acc = ffma2(w.y, hx[2 * k2 + 1], acc);
    }
    return acc;
}

__global__ __launch_bounds__(128)
void gru_kernel(const float* __restrict__ w_ih, const float* __restrict__ w_hh,
                const float* __restrict__ b_ih, const float* __restrict__ b_hh,
                const float* __restrict__ w_fc, const float* __restrict__ b_fc,
                float* __restrict__ out)
{
    __shared__ ull w4p[4 * QSTRIDE];

    int tid = threadIdx.x;
    for (int idx = tid; idx < 4 * 192; idx += 128) {
        int q    = idx / 192;
        int rem  = idx % 192;
        int r    = rem / 16;
        int kk   = rem % 16;
        int gate = r >> 2;
        int jj   = r & 3;
        int row  = gate * 16 + q * 4 + jj;
        int srck = ((q ^ (kk >> 2)) << 2) | (kk & 3);
        float v  = w_hh[row * 16 + srck];
        if (gate < 2) v *= 0.5f;              // fold sigmoid half-scale into r,z
        w4p[q * QSTRIDE + r * 16 + kk] = pk2(v, v);
    }
    __syncthreads();

    int g = blockIdx.x * 128 + tid;
    int q = g & 3;
    int p = g >> 2;          // batch-pair index; elements 2p, 2p+1

    // Per-thread packed constants for its 4 hidden indices j = q*4 + jj
    ull wirp[4], wizp[4], winp[4], bsrp[4], bszp[4], binp[4], bhnp[4];
#pragma unroll
    for (int jj = 0; jj < 4; jj++) {
        int j = q * 4 + jj;
        float wr = 0.5f * __ldg(&w_ih[j]);
        float wz = 0.5f * __ldg(&w_ih[16 + j]);
        float wn = __ldg(&w_ih[32 + j]);
        float br = 0.5f * (__ldg(&b_ih[j]) + __ldg(&b_hh[j]));
        float bz = 0.5f * (__ldg(&b_ih[16 + j]) + __ldg(&b_hh[16 + j]));
        float bi = __ldg(&b_ih[32 + j]);
        float bh = __ldg(&b_hh[32 + j]);
        wirp[jj] = pk2(wr, wr); wizp[jj] = pk2(wz, wz); winp[jj] = pk2(wn, wn);
        bsrp[jj] = pk2(br, br); bszp[jj] = pk2(bz, bz);
        binp[jj] = pk2(bi, bi); bhnp[jj] = pk2(bh, bh);
    }
    const ull* wb = &w4p[q * QSTRIDE];

    // hx blocks of 4: [own(q), q^1, q^2, q^3]
    ull hx[16];
#pragma unroll
    for (int k = 0; k < 16; k++) hx[k] = 0ull;

    const float2* xp = ((const float2*)g_xT) + p;
    float2 xv = __ldg(&xp[0]);

    for (int t = 0; t < TT; t++) {
        ull xp2 = pk2(xv.x, xv.y);
        int tn = (t < TT - 1) ? (t + 1) : t;
        float2 xnext = __ldg(&xp[(size_t)tn * (BB / 2)]);

        ull rr[4];
        float z0a[4], z1a[4];

        // r gate (rows 0..3): pre-activation already half-scaled
#pragma unroll
        for (int jj = 0; jj < 4; jj++) {
            ull acc = ffma2(xp2, wirp[jj], bsrp[jj]);
            acc = dot16(wb + jj * 16, hx, acc);
            float a0, a1; upk2(acc, a0, a1);
            rr[jj] = pk2(sig_from_half(a0), sig_from_half(a1));
        }
        // z gate (rows 4..7)
#pragma unroll
        for (int jj = 0; jj < 4; jj++) {
            ull acc = ffma2(xp2, wizp[jj], bszp[jj]);
            acc = dot16(wb + (4 + jj) * 16, hx, acc);
            float a0, a1; upk2(acc, a0, a1);
            z0a[jj] = sig_from_half(a0);
            z1a[jj] = sig_from_half(a1);
        }
        // n gate (rows 8..11) + h update
        ull hnew[4];
#pragma unroll
        for (int jj = 0; jj < 4; jj++) {
            ull gh  = dot16(wb + (8 + jj) * 16, hx, bhnp[jj]);
            ull gi  = ffma2(xp2, winp[jj], binp[jj]);
            ull pre = ffma2(rr[jj], gh, gi);
            float p0, p1; upk2(pre, p0, p1);
            float n0 = tanh_mufu(p0);
            float n1 = tanh_mufu(p1);
            float h0, h1; upk2(hx[jj], h0, h1);
            h0 = fmaf(z0a[jj], h0 - n0, n0);          // (1-z)n + z h
            h1 = fmaf(z1a[jj], h1 - n1, n1);
            hnew[jj] = pk2(h0, h1);
        }
#pragma unroll
        for (int jj = 0; jj < 4; jj++) hx[jj] = hnew[jj];

        // butterfly all-gather within the 4-lane group
#pragma unroll
        for (int jj = 0; jj < 4; jj++) {
            hx[4 + jj] = __shfl_xor_sync(0xffffffffu, hx[jj], 1);
        }
#pragma unroll
        for (int jj = 0; jj < 8; jj++) {
            hx[8 + jj] = __shfl_xor_sync(0xffffffffu, hx[jj], 2);
        }

        xv = xnext;
    }

    // FC epilogue: out[b] = sum_j h[b][j] * w_fc[j] + b_fc
    float p0 = 0.0f, p1 = 0.0f;
#pragma unroll
    for (int jj = 0; jj < 4; jj++) {
        float wf = __ldg(&w_fc[q * 4 + jj]);
        float h0, h1; upk2(hx[jj], h0, h1);
        p0 = fmaf(h0, wf, p0);
        p1 = fmaf(h1, wf, p1);
    }
    p0 += __shfl_xor_sync(0xffffffffu, p0, 1);
    p1 += __shfl_xor_sync(0xffffffffu, p1, 1);
    p0 += __shfl_xor_sync(0xffffffffu, p0, 2);
    p1 += __shfl_xor_sync(0xffffffffu, p1, 2);
    if (q == 0) {
        float bf = __ldg(b_fc);
        float2 o;
        o.x = p0 + bf;
        o.y = p1 + bf;
        *(float2*)(out + 2 * p) = o;
    }
}

// ---------------------------------------------------------------------------
extern "C" void kernel_launch(void* const* d_in, const int* in_sizes, int n_in,
                              void* d_out, int out_size)
{
    const float* x    = (const float*)d_in[0];
    const float* w_ih = (const float*)d_in[1];
    const float* w_hh = (const float*)d_in[2];
    const float* b_ih = (const float*)d_in[3];
    const float* b_hh = (const float*)d_in[4];
    const float* w_fc = (const float*)d_in[5];
    const float* b_fc = (const float*)d_in[6];
    float* out = (float*)d_out;

    dim3 tb(32, 8);
    dim3 tg(TT / 32, BB / 32);
    transpose_kernel<<<tg, tb>>>(x);

    // 16384 batch / 2 per 4-lane group * 4 lanes = 32768 threads
    gru_kernel<<<256, 128>>>(w_ih, w_hh, b_ih, b_hh, w_fc, b_fc, out);
}

// round 4
// speedup vs baseline: 8.9598x; 2.9199x over previous
#include <cuda_runtime.h>
#include <cstdint>

#define BB 16384
#define TT 2048

// Scratch: x transposed to [T, B] so the GRU kernel's per-step load is coalesced.
__device__ float g_xT[(size_t)BB * (size_t)TT];

typedef unsigned long long ull;

__device__ __forceinline__ ull pk2(float a, float b) {
    ull r; asm("mov.b64 %0, {%1, %2};" : "=l"(r) : "f"(a), "f"(b)); return r;
}
__device__ __forceinline__ void upk2(ull v, float& a, float& b) {
    asm("mov.b64 {%0, %1}, %2;" : "=f"(a), "=f"(b) : "l"(v));
}
__device__ __forceinline__ ull ffma2(ull a, ull b, ull c) {
    ull d; asm("fma.rn.f32x2 %0, %1, %2, %3;" : "=l"(d) : "l"(a), "l"(b), "l"(c)); return d;
}
// MUFU.TANH — single-instruction tanh (sm_75+)
__device__ __forceinline__ float tanh_mufu(float x) {
    float y; asm("tanh.approx.f32 %0, %1;" : "=f"(y) : "f"(x)); return y;
}
// sigmoid with the 0.5 input scale PRE-FOLDED into weights/biases:
// caller passes a = 0.5*(gi+gh); sigmoid = 0.5*tanh(a) + 0.5
__device__ __forceinline__ float sig_from_half(float a) {
    return fmaf(0.5f, tanh_mufu(a), 0.5f);
}

// ---------------------------------------------------------------------------
// Kernel 1: transpose x [B, T] -> g_xT [T, B]
// ---------------------------------------------------------------------------
__global__ void transpose_kernel(const float* __restrict__ x) {
    __shared__ float tile[32][33];
    int t0 = blockIdx.x * 32;
    int b0 = blockIdx.y * 32;
    int tx = threadIdx.x, ty = threadIdx.y;
#pragma unroll
    for (int i = 0; i < 4; i++) {
        tile[ty + i * 8][tx] = x[(size_t)(b0 + ty + i * 8) * TT + (t0 + tx)];
    }
    __syncthreads();
#pragma unroll
    for (int i = 0; i < 4; i++) {
        g_xT[(size_t)(t0 + ty + i * 8) * BB + (b0 + tx)] = tile[tx][ty + i * 8];
    }
}

// ---------------------------------------------------------------------------
// Kernel 2: GRU scan, 16-way hidden split, register-resident weights.
//   - 16-lane group handles one packed batch pair (f32x2 over 2 elements).
//   - Lane j (= tid & 15) owns hidden index j and gate rows {j, 16+j, 32+j}.
//     All 48 row weights live in registers as (w,w) f32x2 — zero LDS for
//     weights in the inner loop.
//   - Per-step h exchange: STS.64 own h -> double-buffered SMEM slot,
//     __syncwarp, 8x LDS.128 to reload all 16 h values. Pair slots padded to
//     20 ull so the warp's two pairs sit 8 banks apart (conflict-free).
//   - r/z weights+biases pre-scaled by 0.5 (sigmoid via tanh identity).
// ---------------------------------------------------------------------------

#define QPAD 20   // ull per pair slot (16 + 4 pad -> 8-bank offset between pairs)

__global__ __launch_bounds__(128)
void gru_kernel(const float* __restrict__ w_ih, const float* __restrict__ w_hh,
                const float* __restrict__ b_ih, const float* __restrict__ b_hh,
                const float* __restrict__ w_fc, const float* __restrict__ b_fc,
                float* __restrict__ out)
{
    __shared__ ull hbuf[2][8][QPAD];

    int tid = threadIdx.x;
    int g   = blockIdx.x * 128 + tid;
    int j   = g & 15;          // owned hidden index
    int p   = g >> 4;          // global batch-pair index (elements 2p, 2p+1)
    int pb  = tid >> 4;        // pair slot within block (0..7)

    // --- register-resident recurrent weights (duplicated f32x2) ---
    ull wr_[16], wz_[16], wn_[16];
#pragma unroll
    for (int k = 0; k < 16; k++) {
        float a = 0.5f * __ldg(&w_hh[j * 16 + k]);          // r row, half-scaled
        float b = 0.5f * __ldg(&w_hh[(16 + j) * 16 + k]);   // z row, half-scaled
        float c = __ldg(&w_hh[(32 + j) * 16 + k]);          // n row
        wr_[k] = pk2(a, a);
        wz_[k] = pk2(b, b);
        wn_[k] = pk2(c, c);
    }

    // --- gate-input constants ---
    float wirf = 0.5f * __ldg(&w_ih[j]);
    float wizf = 0.5f * __ldg(&w_ih[16 + j]);
    float winf = __ldg(&w_ih[32 + j]);
    float bsrf = 0.5f * (__ldg(&b_ih[j]) + __ldg(&b_hh[j]));
    float bszf = 0.5f * (__ldg(&b_ih[16 + j]) + __ldg(&b_hh[16 + j]));
    float binf = __ldg(&b_ih[32 + j]);
    float bhnf = __ldg(&b_hh[32 + j]);
    ull wirp = pk2(wirf, wirf), wizp = pk2(wizf, wizf), winp = pk2(winf, winf);
    ull bsrp = pk2(bsrf, bsrf), bszp = pk2(bszf, bszf);
    ull binp = pk2(binf, binf), bhnp = pk2(bhnf, bhnf);

    // hx[k] = packed h_k for both elements; hown = own h_j (avoids runtime
    // indexing into the register array)
    ull hx[16];
#pragma unroll
    for (int k = 0; k < 16; k++) hx[k] = 0ull;
    ull hown = 0ull;

    const float2* xp = ((const float2*)g_xT) + p;
    float2 xv = __ldg(&xp[0]);

    int buf = 0;
    for (int t = 0; t < TT; t++) {
        ull x2 = pk2(xv.x, xv.y);
        int tn = (t < TT - 1) ? (t + 1) : t;
        float2 xnext = __ldg(&xp[(size_t)tn * (BB / 2)]);

        // three gate pre-activations (independent FMA chains)
        ull aR = ffma2(x2, wirp, bsrp);
        ull aZ = ffma2(x2, wizp, bszp);
        ull aN = bhnp;
#pragma unroll
        for (int k = 0; k < 16; k++) {
            aR = ffma2(wr_[k], hx[k], aR);
            aZ = ffma2(wz_[k], hx[k], aZ);
            aN = ffma2(wn_[k], hx[k], aN);
        }

        float a0, a1;
        upk2(aR, a0, a1);
        ull rr = pk2(sig_from_half(a0), sig_from_half(a1));
        float z0, z1;
        upk2(aZ, z0, z1);
        z0 = sig_from_half(z0);
        z1 = sig_from_half(z1);

        ull gi  = ffma2(x2, winp, binp);
        ull pre = ffma2(rr, aN, gi);
        float p0, p1;
        upk2(pre, p0, p1);
        float n0 = tanh_mufu(p0);
        float n1 = tanh_mufu(p1);

        float h0, h1;
        upk2(hown, h0, h1);
        h0 = fmaf(z0, h0 - n0, n0);    // (1-z)n + z h
        h1 = fmaf(z1, h1 - n1, n1);
        hown = pk2(h0, h1);

        // exchange: write own h, sync, reload all 16
        hbuf[buf][pb][j] = hown;
        __syncwarp();
#pragma unroll
        for (int k2 = 0; k2 < 8; k2++) {
            ulonglong2 v = *(const ulonglong2*)&hbuf[buf][pb][2 * k2];
            hx[2 * k2]     = v.x;
            hx[2 * k2 + 1] = v.y;
        }
        buf ^= 1;

        xv = xnext;
    }

    // FC epilogue: out[b] = sum_j h[b][j] * w_fc[j] + b_fc
    float wf = __ldg(&w_fc[j]);
    float h0, h1;
    upk2(hown, h0, h1);
    float s0 = h0 * wf;
    float s1 = h1 * wf;
#pragma unroll
    for (int d = 1; d < 16; d <<= 1) {
        s0 += __shfl_xor_sync(0xffffffffu, s0, d);
        s1 += __shfl_xor_sync(0xffffffffu, s1, d);
    }
    if (j == 0) {
        float bf = __ldg(b_fc);
        float2 o;
        o.x = s0 + bf;
        o.y = s1 + bf;
        *(float2*)(out + 2 * p) = o;
    }
}

// ---------------------------------------------------------------------------
extern "C" void kernel_launch(void* const* d_in, const int* in_sizes, int n_in,
                              void* d_out, int out_size)
{
    const float* x    = (const float*)d_in[0];
    const float* w_ih = (const float*)d_in[1];
    const float* w_hh = (const float*)d_in[2];
    const float* b_ih = (const float*)d_in[3];
    const float* b_hh = (const float*)d_in[4];
    const float* w_fc = (const float*)d_in[5];
    const float* b_fc = (const float*)d_in[6];
    float* out = (float*)d_out;

    dim3 tb(32, 8);
    dim3 tg(TT / 32, BB / 32);
    transpose_kernel<<<tg, tb>>>(x);

    // 16384 batch / 2 per 16-lane group * 16 lanes = 131072 threads
    gru_kernel<<<1024, 128>>>(w_ih, w_hh, b_ih, b_hh, w_fc, b_fc, out);
}